// round 9
// baseline (speedup 1.0000x reference)
#include <cuda_runtime.h>
#include <cuda_fp16.h>
#include <math.h>

#define NN 40000
#define EE 640000
#define D  128
#define DOUT 40
#define D3P 64                // padded fp16 width for layer-3 features
#define GR 64
#define GBB 160
#define PER 250

// ---------------- scratch ----------------------------------------------------
__device__ int     g_degD[NN];
__device__ float   g_dis[NN];
__device__ int     g_rowptr[NN + 1];
__device__ int     g_cursor[NN];
__device__ int     g_csrc[EE];
__device__ float   g_cnorm[EE];
__device__ __half2 g_hH[NN * (D / 2)];     // fp16 hidden, 256B/row
__device__ float   g_y [NN * D];
__device__ __half  g_h3[NN * D3P];         // fp16 layer-3 features, 128B/row
__device__ int     g_part[GBB];
__device__ int     g_gbar[4];
__device__ unsigned int g_reg;

// ---------------- edge pass: in-degree histogram + reset flags ----------------
__global__ void k_deg(const int* __restrict__ dst, int E) {
    int e = blockIdx.x * blockDim.x + threadIdx.x;
    if (e == 0) { g_gbar[0] = 0; g_gbar[1] = 0; g_gbar[2] = 0; g_reg = 0u; }
    if (e < E) atomicAdd(&g_degD[dst[e]], 1);
}

__device__ __forceinline__ void grid_bar(int slot) {
    __syncthreads();
    if (threadIdx.x == 0) {
        __threadfence();
        atomicAdd(&g_gbar[slot], 1);
        while (atomicAdd(&g_gbar[slot], 0) < GBB) { }
        __threadfence();
    }
    __syncthreads();
}

// ---------------- fused graph build -------------------------------------------
__global__ __launch_bounds__(256) void k_graph(const int* __restrict__ src,
                                               const int* __restrict__ dst,
                                               int E, int n) {
    const int tid = threadIdx.x;
    const int bid = blockIdx.x;
    __shared__ int sm[256];
    __shared__ int sp[256];
    __shared__ int s_boff;

    const int lo = bid * PER;
    int v = (tid < PER) ? g_degD[lo + tid] : 0;
    sm[tid] = v;
    __syncthreads();
#pragma unroll
    for (int o = 128; o; o >>= 1) {
        if (tid < o) sm[tid] += sm[tid + o];
        __syncthreads();
    }
    if (tid == 0) g_part[bid] = sm[0];
    grid_bar(0);

    sp[tid] = (tid < GBB) ? g_part[tid] : 0;
    __syncthreads();
    for (int o = 1; o < 256; o <<= 1) {
        int u = (tid >= o) ? sp[tid - o] : 0;
        __syncthreads();
        sp[tid] += u;
        __syncthreads();
    }
    if (tid == 0) s_boff = (bid == 0) ? 0 : sp[bid - 1];
    __syncthreads();
    const int boff = s_boff;

    sm[tid] = v;
    __syncthreads();
    for (int o = 1; o < 256; o <<= 1) {
        int u = (tid >= o) ? sm[tid - o] : 0;
        __syncthreads();
        sm[tid] += u;
        __syncthreads();
    }
    if (tid < PER) {
        int i = lo + tid;
        int excl = boff + sm[tid] - v;
        g_rowptr[i] = excl;
        g_cursor[i] = excl;
        g_dis[i] = rsqrtf((float)(v + 1));
        g_degD[i] = 0;
    }
    if (bid == GBB - 1 && tid == 0) g_rowptr[n] = E;
    grid_bar(1);

    const int gt = bid * 256 + tid;
    const int gs = GBB * 256;
    for (int e = gt; e < E; e += gs) {
        int s = src[e], d = dst[e];
        int pos = atomicAdd(&g_cursor[d], 1);
        g_csrc[pos]  = s;
        g_cnorm[pos] = g_dis[s] * g_dis[d];
    }
    grid_bar(2);

    for (int e = gt; e < E; e += gs) {
        int s = src[e], d = dst[e];
        int p  = g_rowptr[s];
        int pe = g_rowptr[s + 1];
        int c = 0;
        for (; p < pe; p++) c += (g_csrc[p] == d);
        if (c) atomicAdd(&g_reg, (unsigned int)c);
    }
}

// ---------------- SGEMM [M,128]@[128,128] -> fp16 H ---------------------------
__global__ __launch_bounds__(256) void k_gemm128(const float* __restrict__ X,
                                                 const float* __restrict__ W,
                                                 const float* __restrict__ bias,
                                                 int act,
                                                 __half2* __restrict__ Hh, int M) {
    extern __shared__ float smf[];
    float* Ws = smf;
    float* Xs = smf + D * D;
    __shared__ float4 bs4[32];
    for (int i = threadIdx.x; i < D * D; i += 256) Ws[i] = W[i];
    if (threadIdx.x < 32)
        bs4[threadIdx.x] = act ? ((const float4*)bias)[threadIdx.x]
                               : make_float4(0.f, 0.f, 0.f, 0.f);

    const int tx = threadIdx.x & 31;
    const int ty = threadIdx.x >> 5;
    const int t0 = blockIdx.x * GR;

    __syncthreads();
    const float4* Xg = (const float4*)(X + (size_t)t0 * D);
    float4* Xs4 = (float4*)Xs;
    for (int i = threadIdx.x; i < GR * (D / 4); i += 256) {
        float4 xv = Xg[i];
        if (act) {
            float4 bb = bs4[i & 31];
            xv.x = fmaxf(xv.x + bb.x, 0.f);
            xv.y = fmaxf(xv.y + bb.y, 0.f);
            xv.z = fmaxf(xv.z + bb.z, 0.f);
            xv.w = fmaxf(xv.w + bb.w, 0.f);
        }
        Xs4[i] = xv;
    }
    __syncthreads();

    float4 acc[8];
#pragma unroll
    for (int r = 0; r < 8; r++) acc[r] = make_float4(0.f, 0.f, 0.f, 0.f);

    const float* xrow = Xs + ty * 8 * D;
#pragma unroll 4
    for (int k = 0; k < D; k++) {
        float4 wv = *(const float4*)&Ws[k * D + tx * 4];
#pragma unroll
        for (int r = 0; r < 8; r++) {
            float xv = xrow[r * D + k];
            acc[r].x += xv * wv.x;
            acc[r].y += xv * wv.y;
            acc[r].z += xv * wv.z;
            acc[r].w += xv * wv.w;
        }
    }
    uint2* Hg = (uint2*)Hh;
#pragma unroll
    for (int r = 0; r < 8; r++) {
        int row = t0 + ty * 8 + r;
        __half2 h01 = __floats2half2_rn(acc[r].x, acc[r].y);
        __half2 h23 = __floats2half2_rn(acc[r].z, acc[r].w);
        uint2 u;
        u.x = *(unsigned int*)&h01;
        u.y = *(unsigned int*)&h23;
        Hg[(size_t)row * 32 + tx] = u;
    }
}

// ---------------- SGEMM [M,128]@[128,40] -> fp16 H3 (padded 64) ---------------
__global__ __launch_bounds__(256) void k_gemm40(const float* __restrict__ X,
                                                const float* __restrict__ W,
                                                const float* __restrict__ bias,
                                                __half* __restrict__ H3, int M) {
    __shared__ float Ws[D * DOUT];
    __shared__ float Xs[GR * D];
    __shared__ float4 bs4[32];
    for (int i = threadIdx.x; i < D * DOUT; i += 256) Ws[i] = W[i];
    if (threadIdx.x < 32) bs4[threadIdx.x] = ((const float4*)bias)[threadIdx.x];

    const int tx = threadIdx.x & 7;
    const int ty = threadIdx.x >> 3;
    const int t0 = blockIdx.x * GR;

    __syncthreads();
    const float4* Xg = (const float4*)(X + (size_t)t0 * D);
    float4* Xs4 = (float4*)Xs;
    for (int i = threadIdx.x; i < GR * (D / 4); i += 256) {
        float4 xv = Xg[i];
        float4 bb = bs4[i & 31];
        xv.x = fmaxf(xv.x + bb.x, 0.f);
        xv.y = fmaxf(xv.y + bb.y, 0.f);
        xv.z = fmaxf(xv.z + bb.z, 0.f);
        xv.w = fmaxf(xv.w + bb.w, 0.f);
        Xs4[i] = xv;
    }
    __syncthreads();

    float a0[5] = {0, 0, 0, 0, 0};
    float a1[5] = {0, 0, 0, 0, 0};
    const float* x0 = Xs + (ty * 2) * D;
#pragma unroll 4
    for (int k = 0; k < D; k++) {
        float w[5];
#pragma unroll
        for (int j = 0; j < 5; j++) w[j] = Ws[k * DOUT + tx * 5 + j];
        float xa = x0[k];
        float xb = x0[D + k];
#pragma unroll
        for (int j = 0; j < 5; j++) {
            a0[j] += xa * w[j];
            a1[j] += xb * w[j];
        }
    }
    int r0 = t0 + ty * 2;
    __half* o0 = H3 + (size_t)r0 * D3P + tx * 5;
#pragma unroll
    for (int j = 0; j < 5; j++) {
        o0[j]       = __float2half(a0[j]);
        o0[D3P + j] = __float2half(a1[j]);
    }
    // zero the pad cols 40..63 (3 halfs per tx per row)
    __half* z0 = H3 + (size_t)r0 * D3P + DOUT + tx * 3;
#pragma unroll
    for (int j = 0; j < 3; j++) { z0[j] = __float2half(0.f); z0[D3P + j] = __float2half(0.f); }
}

// ---------------- aggregation (128-d): paired-edge 16-lane fp16 gathers -------
__global__ __launch_bounds__(256) void k_agg128(const __half2* __restrict__ Hh,
                                                float* __restrict__ Y, int n) {
    __shared__ int   ss[8][32];
    __shared__ float sw[8][32];
    const int lane = threadIdx.x & 31;
    const int wrp  = threadIdx.x >> 5;
    const int hw   = lane >> 4;        // 0 = edge j, 1 = edge j+1
    const int hl   = lane & 15;        // 16B chunk within row
    const int i = blockIdx.x * 8 + wrp;
    if (i >= n) return;

    const uint4* __restrict__ Hu4 = (const uint4*)Hh;   // 16 uint4 per row

    float acc[8];
#pragma unroll
    for (int k = 0; k < 8; k++) acc[k] = 0.f;

    int p = g_rowptr[i];
    const int pe = g_rowptr[i + 1];
    while (p < pe) {
        int cnt = pe - p;
        if (cnt > 32) cnt = 32;
        if (lane < cnt) {
            ss[wrp][lane] = g_csrc[p + lane];
            sw[wrp][lane] = g_cnorm[p + lane];
        }
        __syncwarp();
        for (int j = 0; j < cnt; j += 2) {
            int jj = j + hw;
            bool valid = jj < cnt;
            int   s = valid ? ss[wrp][jj] : 0;
            float w = valid ? sw[wrp][jj] : 0.f;
            uint4 u = Hu4[(size_t)s * 16 + hl];
            float2 f0 = __half22float2(*(__half2*)&u.x);
            float2 f1 = __half22float2(*(__half2*)&u.y);
            float2 f2 = __half22float2(*(__half2*)&u.z);
            float2 f3 = __half22float2(*(__half2*)&u.w);
            acc[0] += w * f0.x; acc[1] += w * f0.y;
            acc[2] += w * f1.x; acc[3] += w * f1.y;
            acc[4] += w * f2.x; acc[5] += w * f2.y;
            acc[6] += w * f3.x; acc[7] += w * f3.y;
        }
        __syncwarp();
        p += cnt;
    }

    // combine the two half-warps
#pragma unroll
    for (int k = 0; k < 8; k++)
        acc[k] += __shfl_xor_sync(0xffffffffu, acc[k], 16);

    if (hw == 0) {
        // self term + store (lanes 0-15, 8 floats each)
        float d2 = g_dis[i]; d2 *= d2;
        uint4 u = Hu4[(size_t)i * 16 + hl];
        float2 f0 = __half22float2(*(__half2*)&u.x);
        float2 f1 = __half22float2(*(__half2*)&u.y);
        float2 f2 = __half22float2(*(__half2*)&u.z);
        float2 f3 = __half22float2(*(__half2*)&u.w);
        acc[0] += d2 * f0.x; acc[1] += d2 * f0.y;
        acc[2] += d2 * f1.x; acc[3] += d2 * f1.y;
        acc[4] += d2 * f2.x; acc[5] += d2 * f2.y;
        acc[6] += d2 * f3.x; acc[7] += d2 * f3.y;
        float4* Yo = (float4*)(Y + (size_t)i * D + hl * 8);
        Yo[0] = make_float4(acc[0], acc[1], acc[2], acc[3]);
        Yo[1] = make_float4(acc[4], acc[5], acc[6], acc[7]);
    }
}

// ---------------- aggregation (40-d fp16 padded) + bias + log_softmax + reg ---
__global__ __launch_bounds__(256) void k_agg40(const __half* __restrict__ H3,
                                               const float* __restrict__ b,
                                               float* __restrict__ out, int n,
                                               int reg_idx) {
    if (blockIdx.x == 0 && threadIdx.x == 0) out[reg_idx] = (float)g_reg;

    __shared__ int   ss[8][32];
    __shared__ float sw[8][32];
    const int lane = threadIdx.x & 31;
    const int wrp  = threadIdx.x >> 5;
    const int hw   = lane >> 4;
    const int hl   = lane & 15;        // owns cols [4hl, 4hl+4)
    const int i = blockIdx.x * 8 + wrp;
    if (i >= n) return;

    const uint2* __restrict__ Hu2 = (const uint2*)H3;   // 16 uint2 per row

    float acc[4] = {0.f, 0.f, 0.f, 0.f};

    int p = g_rowptr[i];
    const int pe = g_rowptr[i + 1];
    while (p < pe) {
        int cnt = pe - p;
        if (cnt > 32) cnt = 32;
        if (lane < cnt) {
            ss[wrp][lane] = g_csrc[p + lane];
            sw[wrp][lane] = g_cnorm[p + lane];
        }
        __syncwarp();
        for (int j = 0; j < cnt; j += 2) {
            int jj = j + hw;
            bool valid = jj < cnt;
            int   s = valid ? ss[wrp][jj] : 0;
            float w = valid ? sw[wrp][jj] : 0.f;
            uint2 u = Hu2[(size_t)s * 16 + hl];
            float2 f0 = __half22float2(*(__half2*)&u.x);
            float2 f1 = __half22float2(*(__half2*)&u.y);
            acc[0] += w * f0.x; acc[1] += w * f0.y;
            acc[2] += w * f1.x; acc[3] += w * f1.y;
        }
        __syncwarp();
        p += cnt;
    }

#pragma unroll
    for (int k = 0; k < 4; k++)
        acc[k] += __shfl_xor_sync(0xffffffffu, acc[k], 16);

    // lanes 0-15 now hold the full 64-wide sums; finish on lower half
    float v[4];
    {
        float d2 = g_dis[i]; d2 *= d2;
        uint2 u = Hu2[(size_t)i * 16 + hl];
        float2 f0 = __half22float2(*(__half2*)&u.x);
        float2 f1 = __half22float2(*(__half2*)&u.y);
        acc[0] += d2 * f0.x; acc[1] += d2 * f0.y;
        acc[2] += d2 * f1.x; acc[3] += d2 * f1.y;
#pragma unroll
        for (int k = 0; k < 4; k++) {
            int col = 4 * hl + k;
            v[k] = (col < DOUT) ? (acc[k] + b[col]) : -INFINITY;
        }
    }

    // softmax over 40 values spread 4-per-lane across lanes 0-9 (xor stays in half)
    float m = fmaxf(fmaxf(v[0], v[1]), fmaxf(v[2], v[3]));
#pragma unroll
    for (int o = 8; o; o >>= 1) m = fmaxf(m, __shfl_xor_sync(0xffffffffu, m, o));
    float se = 0.f;
#pragma unroll
    for (int k = 0; k < 4; k++) se += (v[k] == -INFINITY) ? 0.f : expf(v[k] - m);
#pragma unroll
    for (int o = 8; o; o >>= 1) se += __shfl_xor_sync(0xffffffffu, se, o);
    float ls = m + logf(se);

    if (hw == 0 && hl < 10) {
        float4 o4 = make_float4(v[0] - ls, v[1] - ls, v[2] - ls, v[3] - ls);
        *(float4*)(out + (size_t)i * DOUT + 4 * hl) = o4;
    }
}

// ---------------- launch --------------------------------------------------------
extern "C" void kernel_launch(void* const* d_in, const int* in_sizes, int n_in,
                              void* d_out, int out_size) {
    const float* x  = (const float*)d_in[0];
    const int*   ei = (const int*)d_in[1];
    const float* W1 = (const float*)d_in[2];
    const float* b1 = (const float*)d_in[3];
    const float* W2 = (const float*)d_in[4];
    const float* b2 = (const float*)d_in[5];
    const float* W3 = (const float*)d_in[6];
    const float* b3 = (const float*)d_in[7];
    float* out = (float*)d_out;

    const int n = in_sizes[0] / D;      // 40000
    const int E = in_sizes[1] / 2;      // 640000
    const int* src = ei;
    const int* dst = ei + E;

    const int GEMM_SMEM = (D * D + GR * D) * sizeof(float);  // 96 KB
    cudaFuncSetAttribute(k_gemm128, cudaFuncAttributeMaxDynamicSharedMemorySize, GEMM_SMEM);

    const int TB = 256;
    const int eblocks = (E + TB - 1) / TB;
    const int ablocks = (n + 7) / 8;
    const int gblocks = (n + GR - 1) / GR;

    k_gemm128<<<gblocks, TB, GEMM_SMEM>>>(x, W1, b1, 0, g_hH, n);
    k_deg<<<eblocks, TB>>>(dst, E);
    k_graph<<<GBB, TB>>>(src, dst, E, n);
    k_agg128<<<ablocks, TB>>>(g_hH, g_y, n);          // profiled launch
    k_gemm128<<<gblocks, TB, GEMM_SMEM>>>(g_y, W2, b1, 1, g_hH, n);
    k_agg128<<<ablocks, TB>>>(g_hH, g_y, n);
    k_gemm40<<<gblocks, TB>>>(g_y, W3, b2, g_h3, n);
    k_agg40<<<ablocks, TB>>>(g_h3, b3, out, n, out_size - 1);
}